// round 5
// baseline (speedup 1.0000x reference)
#include <cuda_runtime.h>
#include <math_constants.h>

// TropicalLinear: out[n,o] = max_k( x[n,k] + w[o,k] ) + bias[o]
// N=128, IN=1024, OUT=1024, fp32. Exact max-plus matmul (STE term == 0 fwd).
//
// v4b (resubmit after infra failure): 4x8 micro-tile -> crossbar demand 72%
//     of issue (was 100%), KC=64 / KSPLIT=16 for 4 CTAs/SM single wave,
//     fused last-CTA reduction via atomic ticket.

#define BN 32
#define BO 128
#define KC 64
#define ROWF (KC + 4)          // 68 floats: odd 16B-granule stride -> conflict-free LDS.128
#define NTHREADS 128
#define KSPLIT 16

#define N_TOT 128
#define IN_TOT 1024
#define OUT_TOT 1024

#define TILES_O (OUT_TOT / BO)   // 8
#define TILES_N (N_TOT / BN)     // 4

__device__ float g_partial[KSPLIT * N_TOT * OUT_TOT];   // [kz][n][o]  (8MB)
__device__ int   g_ticket[TILES_N * TILES_O];           // zero-init; self-resetting

__global__ __launch_bounds__(NTHREADS, 4)
void tropical_kernel(const float* __restrict__ x,     // [N, IN]
                     const float* __restrict__ w,     // [OUT, IN]
                     const float* __restrict__ bias,  // [OUT]
                     float* __restrict__ out)         // [N, OUT]
{
    __shared__ float xs[BN][ROWF];
    __shared__ float ws[BO][ROWF];
    __shared__ int   s_last;

    const int t = threadIdx.x;
    const int o_base = blockIdx.x * BO;
    const int n_base = blockIdx.y * BN;
    const int kz     = blockIdx.z;
    const int kc     = kz * KC;            // single K-chunk per CTA

    // thread grid 16(o) x 8(n); micro-tile 4(n) x 8(o)
    const int tx = t & 15;                 // o rows: tx + j*16, j=0..7
    const int ty = t >> 4;                 // n rows: ty + i*8,  i=0..3

    // ---- stage tiles (coalesced LDG.128 -> STS.128), 16 float4 cols/row ----
    #pragma unroll
    for (int i = 0; i < BN * KC / 4 / NTHREADS; i++) {    // 4 iters
        int idx  = t + i * NTHREADS;
        int row  = idx >> 4;
        int col4 = idx & 15;
        *reinterpret_cast<float4*>(&xs[row][col4 * 4]) =
            *reinterpret_cast<const float4*>(&x[(n_base + row) * IN_TOT + kc + col4 * 4]);
    }
    #pragma unroll
    for (int i = 0; i < BO * KC / 4 / NTHREADS; i++) {    // 16 iters
        int idx  = t + i * NTHREADS;
        int row  = idx >> 4;
        int col4 = idx & 15;
        *reinterpret_cast<float4*>(&ws[row][col4 * 4]) =
            *reinterpret_cast<const float4*>(&w[(o_base + row) * IN_TOT + kc + col4 * 4]);
    }
    __syncthreads();

    // ---- mainloop: 12 LDS.128 feed 256 FADD+FMNMX per k4 ----
    float acc[4][8];
    #pragma unroll
    for (int i = 0; i < 4; i++)
        #pragma unroll
        for (int j = 0; j < 8; j++)
            acc[i][j] = -CUDART_INF_F;

    #pragma unroll 4
    for (int k4 = 0; k4 < KC / 4; k4++) {
        float4 xv[4], wv[8];
        #pragma unroll
        for (int i = 0; i < 4; i++)
            xv[i] = *reinterpret_cast<const float4*>(&xs[ty + i * 8][k4 * 4]);
        #pragma unroll
        for (int j = 0; j < 8; j++)
            wv[j] = *reinterpret_cast<const float4*>(&ws[tx + j * 16][k4 * 4]);

        #pragma unroll
        for (int i = 0; i < 4; i++) {
            #pragma unroll
            for (int j = 0; j < 8; j++) {
                acc[i][j] = fmaxf(acc[i][j], xv[i].x + wv[j].x);
                acc[i][j] = fmaxf(acc[i][j], xv[i].y + wv[j].y);
                acc[i][j] = fmaxf(acc[i][j], xv[i].z + wv[j].z);
                acc[i][j] = fmaxf(acc[i][j], xv[i].w + wv[j].w);
            }
        }
    }

    // ---- write split-K partial (lanes 0-15 contiguous per (i,j)) ----
    float* p = g_partial + kz * (N_TOT * OUT_TOT);
    #pragma unroll
    for (int i = 0; i < 4; i++) {
        #pragma unroll
        for (int j = 0; j < 8; j++) {
            p[(n_base + ty + i * 8) * OUT_TOT + o_base + tx + j * 16] = acc[i][j];
        }
    }

    // ---- last CTA per (n,o)-tile reduces across kz ----
    __threadfence();
    __syncthreads();
    const int tile = blockIdx.y * TILES_O + blockIdx.x;
    if (t == 0) {
        int old = atomicAdd(&g_ticket[tile], 1);
        s_last = (old == KSPLIT - 1);
        if (s_last) g_ticket[tile] = 0;   // reset for next graph replay
    }
    __syncthreads();

    if (s_last) {
        __threadfence();   // acquire: all partials visible
        // tile = BN x BO = 4096 floats = 1024 float4; 128 threads * 8 float4
        #pragma unroll
        for (int j = 0; j < 8; j++) {
            int f   = j * NTHREADS + t;          // float4 index within tile
            int ln  = f >> 5;                    // 32 float4 per 128-o row
            int lo4 = f & 31;
            int base = (n_base + ln) * OUT_TOT + o_base + lo4 * 4;

            float4 m = *reinterpret_cast<const float4*>(&g_partial[base]);
            #pragma unroll
            for (int z = 1; z < KSPLIT; z++) {
                float4 v = *reinterpret_cast<const float4*>(
                    &g_partial[z * (N_TOT * OUT_TOT) + base]);
                m.x = fmaxf(m.x, v.x);
                m.y = fmaxf(m.y, v.y);
                m.z = fmaxf(m.z, v.z);
                m.w = fmaxf(m.w, v.w);
            }
            float4 b = *reinterpret_cast<const float4*>(&bias[o_base + lo4 * 4]);
            m.x += b.x; m.y += b.y; m.z += b.z; m.w += b.w;
            *reinterpret_cast<float4*>(&out[base]) = m;
        }
    }
}

extern "C" void kernel_launch(void* const* d_in, const int* in_sizes, int n_in,
                              void* d_out, int out_size) {
    const float* x    = (const float*)d_in[0];   // [128, 1024]
    const float* w    = (const float*)d_in[1];   // [1024, 1024]
    const float* bias = (const float*)d_in[2];   // [1024]
    float* out        = (float*)d_out;           // [128, 1024]

    dim3 grid(TILES_O, TILES_N, KSPLIT);         // 8 x 4 x 16 = 512 CTAs
    tropical_kernel<<<grid, NTHREADS>>>(x, w, bias, out);
}

// round 6
// speedup vs baseline: 1.0531x; 1.0531x over previous
#include <cuda_runtime.h>
#include <math_constants.h>

// TropicalLinear: out[n,o] = max_k( x[n,k] + w[o,k] ) + bias[o]
// N=128, IN=1024, OUT=1024, fp32. Exact max-plus matmul (STE term == 0 fwd).
//
// v5: occupancy push. 4x4 micro-tile, 64-reg cap via __launch_bounds__(128,8)
//     -> 8 CTAs/SM = 32 warps/SM (was 16). KC=64, KSPLIT=16, 1024 CTAs,
//     single wave, fused last-CTA reduction. Pipe floors (fma=FADD,
//     alu=FMNMX, 1:1) give a 7.5us floor; this round targets issue ~75%.

#define BN 32
#define BO 64
#define KC 64
#define ROWF (KC + 4)          // 68: ws 16-lane float4 reads tile banks in exactly 2 phases
#define NTHREADS 128
#define KSPLIT 16

#define N_TOT 128
#define IN_TOT 1024
#define OUT_TOT 1024

#define TILES_O (OUT_TOT / BO)   // 16
#define TILES_N (N_TOT / BN)     // 4

__device__ float g_partial[KSPLIT * N_TOT * OUT_TOT];   // [kz][n][o]  (8MB)
__device__ int   g_ticket[TILES_N * TILES_O];           // zero-init; self-resetting

__global__ __launch_bounds__(NTHREADS, 8)
void tropical_kernel(const float* __restrict__ x,     // [N, IN]
                     const float* __restrict__ w,     // [OUT, IN]
                     const float* __restrict__ bias,  // [OUT]
                     float* __restrict__ out)         // [N, OUT]
{
    __shared__ float xs[BN][ROWF];
    __shared__ float ws[BO][ROWF];
    __shared__ int   s_last;

    const int t = threadIdx.x;
    const int o_base = blockIdx.x * BO;
    const int n_base = blockIdx.y * BN;
    const int kz     = blockIdx.z;
    const int kc     = kz * KC;            // single K-chunk per CTA

    // thread grid 16(o) x 8(n); micro-tile 4(n) x 4(o)
    const int tx = t & 15;                 // o rows: tx + j*16, j=0..3
    const int ty = t >> 4;                 // n rows: ty + i*8,  i=0..3

    // ---- stage tiles (coalesced LDG.128 -> STS.128), 16 float4 per row ----
    #pragma unroll
    for (int i = 0; i < BN * KC / 4 / NTHREADS; i++) {    // 4 iters
        int idx  = t + i * NTHREADS;
        int row  = idx >> 4;
        int col4 = idx & 15;
        *reinterpret_cast<float4*>(&xs[row][col4 * 4]) =
            *reinterpret_cast<const float4*>(&x[(n_base + row) * IN_TOT + kc + col4 * 4]);
    }
    #pragma unroll
    for (int i = 0; i < BO * KC / 4 / NTHREADS; i++) {    // 8 iters
        int idx  = t + i * NTHREADS;
        int row  = idx >> 4;
        int col4 = idx & 15;
        *reinterpret_cast<float4*>(&ws[row][col4 * 4]) =
            *reinterpret_cast<const float4*>(&w[(o_base + row) * IN_TOT + kc + col4 * 4]);
    }
    __syncthreads();

    // ---- mainloop: per k4, 4 broadcast xs-LDS + 4 ws-LDS feed 128 FADD+FMNMX ----
    float acc[4][4];
    #pragma unroll
    for (int i = 0; i < 4; i++)
        #pragma unroll
        for (int j = 0; j < 4; j++)
            acc[i][j] = -CUDART_INF_F;

    #pragma unroll 4
    for (int k4 = 0; k4 < KC / 4; k4++) {
        float4 xv[4];
        #pragma unroll
        for (int i = 0; i < 4; i++)
            xv[i] = *reinterpret_cast<const float4*>(&xs[ty + i * 8][k4 * 4]);

        #pragma unroll
        for (int j = 0; j < 4; j++) {
            float4 wv = *reinterpret_cast<const float4*>(&ws[tx + j * 16][k4 * 4]);
            #pragma unroll
            for (int i = 0; i < 4; i++) {
                acc[i][j] = fmaxf(acc[i][j], xv[i].x + wv.x);
                acc[i][j] = fmaxf(acc[i][j], xv[i].y + wv.y);
                acc[i][j] = fmaxf(acc[i][j], xv[i].z + wv.z);
                acc[i][j] = fmaxf(acc[i][j], xv[i].w + wv.w);
            }
        }
    }

    // ---- write split-K partial ----
    float* p = g_partial + kz * (N_TOT * OUT_TOT);
    #pragma unroll
    for (int i = 0; i < 4; i++) {
        #pragma unroll
        for (int j = 0; j < 4; j++) {
            p[(n_base + ty + i * 8) * OUT_TOT + o_base + tx + j * 16] = acc[i][j];
        }
    }

    // ---- last CTA per (n,o)-tile reduces across kz ----
    __threadfence();
    __syncthreads();
    const int tile = blockIdx.y * TILES_O + blockIdx.x;
    if (t == 0) {
        int old = atomicAdd(&g_ticket[tile], 1);
        s_last = (old == KSPLIT - 1);
        if (s_last) g_ticket[tile] = 0;   // reset for next graph replay
    }
    __syncthreads();

    if (s_last) {
        __threadfence();   // acquire: all partials visible
        // tile = BN x BO = 2048 floats = 512 float4; 128 threads * 4 float4
        #pragma unroll
        for (int j = 0; j < 4; j++) {
            int f   = j * NTHREADS + t;          // float4 index within tile
            int ln  = f >> 4;                    // 16 float4 per 64-o row
            int lo4 = f & 15;
            int base = (n_base + ln) * OUT_TOT + o_base + lo4 * 4;

            float4 m = *reinterpret_cast<const float4*>(&g_partial[base]);
            #pragma unroll
            for (int z = 1; z < KSPLIT; z++) {
                float4 v = *reinterpret_cast<const float4*>(
                    &g_partial[z * (N_TOT * OUT_TOT) + base]);
                m.x = fmaxf(m.x, v.x);
                m.y = fmaxf(m.y, v.y);
                m.z = fmaxf(m.z, v.z);
                m.w = fmaxf(m.w, v.w);
            }
            float4 b = *reinterpret_cast<const float4*>(&bias[o_base + lo4 * 4]);
            m.x += b.x; m.y += b.y; m.z += b.z; m.w += b.w;
            *reinterpret_cast<float4*>(&out[base]) = m;
        }
    }
}

extern "C" void kernel_launch(void* const* d_in, const int* in_sizes, int n_in,
                              void* d_out, int out_size) {
    const float* x    = (const float*)d_in[0];   // [128, 1024]
    const float* w    = (const float*)d_in[1];   // [1024, 1024]
    const float* bias = (const float*)d_in[2];   // [1024]
    float* out        = (float*)d_out;           // [128, 1024]

    dim3 grid(TILES_O, TILES_N, KSPLIT);         // 16 x 4 x 16 = 1024 CTAs
    tropical_kernel<<<grid, NTHREADS>>>(x, w, bias, out);
}

// round 7
// speedup vs baseline: 1.1233x; 1.0667x over previous
#include <cuda_runtime.h>
#include <math_constants.h>
#include <cstdint>

// TropicalLinear: out[n,o] = max_k( x[n,k] + w[o,k] ) + bias[o]
// N=128, IN=1024, OUT=1024, fp32. Exact max-plus matmul (STE term == 0 fwd).
//
// v6: latency-duty attack. cp.async 2-stage smem pipeline (4 chunks of K=32
//     per CTA) overlaps fill with compute; explicit register ping-pong
//     prefetch gives LDS->use distance of a full k4 body (~128 instrs).
//     BN32/BO64 4x4 micro-tile, KSPLIT=8, 512 CTAs, fused ticket reduction.

#define BN 32
#define BO 64
#define CHUNK 32
#define NCH 4                    // chunks per CTA -> K_CTA = 128
#define ROWF (CHUNK + 4)         // 36: stride 9x16B (odd) -> conflict-free LDS.128
#define NTHREADS 128
#define KSPLIT 8

#define N_TOT 128
#define IN_TOT 1024
#define OUT_TOT 1024

#define TILES_O (OUT_TOT / BO)   // 16
#define TILES_N (N_TOT / BN)     // 4

__device__ float g_partial[KSPLIT * N_TOT * OUT_TOT];   // 4MB
__device__ int   g_ticket[TILES_N * TILES_O];           // zero-init; self-resetting

__device__ __forceinline__ void cp_async16(uint32_t saddr, const void* gptr) {
    asm volatile("cp.async.cg.shared.global [%0], [%1], 16;"
                 :: "r"(saddr), "l"(gptr) : "memory");
}
__device__ __forceinline__ uint32_t smem_u32(const void* p) {
    return (uint32_t)__cvta_generic_to_shared(p);
}

__global__ __launch_bounds__(NTHREADS, 4)
void tropical_kernel(const float* __restrict__ x,     // [N, IN]
                     const float* __restrict__ w,     // [OUT, IN]
                     const float* __restrict__ bias,  // [OUT]
                     float* __restrict__ out)         // [N, OUT]
{
    __shared__ float xs[2][BN][ROWF];   // 9.2 KB
    __shared__ float ws[2][BO][ROWF];   // 18.4 KB
    __shared__ int   s_last;

    const int t = threadIdx.x;
    const int o_base = blockIdx.x * BO;
    const int n_base = blockIdx.y * BN;
    const int kc0    = blockIdx.z * (NCH * CHUNK);

    const int tx = t & 15;              // o rows: tx + j*16
    const int ty = t >> 4;              // n rows: ty + i*8

    float acc[4][4];
    #pragma unroll
    for (int i = 0; i < 4; i++)
        #pragma unroll
        for (int j = 0; j < 4; j++)
            acc[i][j] = -CUDART_INF_F;

    // ---- async fill of one chunk into buffer b (6 cp.async / thread) ----
    #define FILL(b, kc) do {                                                       \
        _Pragma("unroll")                                                          \
        for (int i = 0; i < 2; i++) {      /* xs: 32 rows x 8 f4 */                \
            int idx = t + i * NTHREADS; int row = idx >> 3; int c4 = idx & 7;      \
            cp_async16(smem_u32(&xs[b][row][c4 * 4]),                              \
                       &x[(n_base + row) * IN_TOT + (kc) + c4 * 4]);               \
        }                                                                          \
        _Pragma("unroll")                                                          \
        for (int i = 0; i < 4; i++) {      /* ws: 64 rows x 8 f4 */                \
            int idx = t + i * NTHREADS; int row = idx >> 3; int c4 = idx & 7;      \
            cp_async16(smem_u32(&ws[b][row][c4 * 4]),                              \
                       &w[(o_base + row) * IN_TOT + (kc) + c4 * 4]);               \
        }                                                                          \
        asm volatile("cp.async.commit_group;" ::: "memory");                       \
    } while (0)

    // ---- compute one chunk with register ping-pong prefetch ----
    #define COMPUTE(b) do {                                                        \
        float4 xv[2][4], wv[2][4];                                                 \
        _Pragma("unroll")                                                          \
        for (int i = 0; i < 4; i++)                                                \
            xv[0][i] = *reinterpret_cast<const float4*>(&xs[b][ty + i * 8][0]);    \
        _Pragma("unroll")                                                          \
        for (int j = 0; j < 4; j++)                                                \
            wv[0][j] = *reinterpret_cast<const float4*>(&ws[b][tx + j * 16][0]);   \
        _Pragma("unroll")                                                          \
        for (int k4 = 0; k4 < CHUNK / 4; k4++) {                                   \
            const int cur = k4 & 1, nxt = cur ^ 1;                                 \
            if (k4 < CHUNK / 4 - 1) {                                              \
                _Pragma("unroll")                                                  \
                for (int i = 0; i < 4; i++)                                        \
                    xv[nxt][i] = *reinterpret_cast<const float4*>(                 \
                        &xs[b][ty + i * 8][(k4 + 1) * 4]);                         \
                _Pragma("unroll")                                                  \
                for (int j = 0; j < 4; j++)                                        \
                    wv[nxt][j] = *reinterpret_cast<const float4*>(                 \
                        &ws[b][tx + j * 16][(k4 + 1) * 4]);                        \
            }                                                                      \
            _Pragma("unroll")                                                      \
            for (int j = 0; j < 4; j++) {                                          \
                _Pragma("unroll")                                                  \
                for (int i = 0; i < 4; i++) {                                      \
                    acc[i][j] = fmaxf(acc[i][j], xv[cur][i].x + wv[cur][j].x);     \
                    acc[i][j] = fmaxf(acc[i][j], xv[cur][i].y + wv[cur][j].y);     \
                    acc[i][j] = fmaxf(acc[i][j], xv[cur][i].z + wv[cur][j].z);     \
                    acc[i][j] = fmaxf(acc[i][j], xv[cur][i].w + wv[cur][j].w);     \
                }                                                                  \
            }                                                                      \
        }                                                                          \
    } while (0)

    // ---- 2-stage pipeline over 4 chunks ----
    FILL(0, kc0);
    FILL(1, kc0 + CHUNK);

    asm volatile("cp.async.wait_group 1;" ::: "memory");   // chunk0 resident
    __syncthreads();
    COMPUTE(0);

    __syncthreads();                                       // all done reading buf0
    FILL(0, kc0 + 2 * CHUNK);
    asm volatile("cp.async.wait_group 1;" ::: "memory");   // chunk1 resident
    __syncthreads();
    COMPUTE(1);

    __syncthreads();                                       // all done reading buf1
    FILL(1, kc0 + 3 * CHUNK);
    asm volatile("cp.async.wait_group 1;" ::: "memory");   // chunk2 resident
    __syncthreads();
    COMPUTE(0);

    asm volatile("cp.async.wait_group 0;" ::: "memory");   // chunk3 resident
    __syncthreads();
    COMPUTE(1);

    // ---- write split-K partial ----
    float* p = g_partial + blockIdx.z * (N_TOT * OUT_TOT);
    #pragma unroll
    for (int i = 0; i < 4; i++) {
        #pragma unroll
        for (int j = 0; j < 4; j++) {
            p[(n_base + ty + i * 8) * OUT_TOT + o_base + tx + j * 16] = acc[i][j];
        }
    }

    // ---- last CTA per (n,o)-tile reduces across kz ----
    __threadfence();
    __syncthreads();
    const int tile = blockIdx.y * TILES_O + blockIdx.x;
    if (t == 0) {
        int old = atomicAdd(&g_ticket[tile], 1);
        s_last = (old == KSPLIT - 1);
        if (s_last) g_ticket[tile] = 0;   // reset for next graph replay
    }
    __syncthreads();

    if (s_last) {
        __threadfence();   // acquire: all partials visible
        #pragma unroll
        for (int j = 0; j < 4; j++) {
            int f    = j * NTHREADS + t;         // 512 float4 per tile
            int ln   = f >> 4;                   // 16 float4 per 64-o row
            int lo4  = f & 15;
            int base = (n_base + ln) * OUT_TOT + o_base + lo4 * 4;

            float4 m = *reinterpret_cast<const float4*>(&g_partial[base]);
            #pragma unroll
            for (int z = 1; z < KSPLIT; z++) {
                float4 v = *reinterpret_cast<const float4*>(
                    &g_partial[z * (N_TOT * OUT_TOT) + base]);
                m.x = fmaxf(m.x, v.x);
                m.y = fmaxf(m.y, v.y);
                m.z = fmaxf(m.z, v.z);
                m.w = fmaxf(m.w, v.w);
            }
            float4 b = *reinterpret_cast<const float4*>(&bias[o_base + lo4 * 4]);
            m.x += b.x; m.y += b.y; m.z += b.z; m.w += b.w;
            *reinterpret_cast<float4*>(&out[base]) = m;
        }
    }
}

extern "C" void kernel_launch(void* const* d_in, const int* in_sizes, int n_in,
                              void* d_out, int out_size) {
    const float* x    = (const float*)d_in[0];   // [128, 1024]
    const float* w    = (const float*)d_in[1];   // [1024, 1024]
    const float* bias = (const float*)d_in[2];   // [1024]
    float* out        = (float*)d_out;           // [128, 1024]

    dim3 grid(TILES_O, TILES_N, KSPLIT);         // 16 x 4 x 8 = 512 CTAs
    tropical_kernel<<<grid, NTHREADS>>>(x, w, bias, out);
}

// round 8
// speedup vs baseline: 1.1661x; 1.0381x over previous
#include <cuda_runtime.h>
#include <math_constants.h>
#include <cstdint>

// TropicalLinear: out[n,o] = max_k( x[n,k] + w[o,k] ) + bias[o]
// N=128, IN=1024, OUT=1024, fp32. Exact max-plus matmul (STE term == 0 fwd).
//
// v7: packed f32x2 adds (Blackwell add.rn.f32x2) halve the FADD count:
//     per (i,j,k4) body 8 -> 6 issue slots (-23%). fmax tree shortens the
//     acc chain. Structure from v6: cp.async 2-stage pipeline, 4x4 tile,
//     BN32/BO64, KSPLIT=8, 512 CTAs, fused last-CTA ticket reduction.

#define BN 32
#define BO 64
#define CHUNK 32
#define NCH 4                    // chunks per CTA -> K_CTA = 128
#define ROWF (CHUNK + 4)         // 36 floats = 9x16B rows: conflict-free LDS.128, 16B aligned
#define NTHREADS 128
#define KSPLIT 8

#define N_TOT 128
#define IN_TOT 1024
#define OUT_TOT 1024

#define TILES_O (OUT_TOT / BO)   // 16
#define TILES_N (N_TOT / BN)     // 4

__device__ float g_partial[KSPLIT * N_TOT * OUT_TOT];   // 4MB
__device__ int   g_ticket[TILES_N * TILES_O];           // zero-init; self-resetting

__device__ __forceinline__ void cp_async16(uint32_t saddr, const void* gptr) {
    asm volatile("cp.async.cg.shared.global [%0], [%1], 16;"
                 :: "r"(saddr), "l"(gptr) : "memory");
}
__device__ __forceinline__ uint32_t smem_u32(const void* p) {
    return (uint32_t)__cvta_generic_to_shared(p);
}

// packed fp32x2 add (sm_103a); unpack via mov.b64 (ptxas aliases to reg pair)
#define ADD_F32X2(out, a, b) \
    asm("add.rn.f32x2 %0, %1, %2;" : "=l"(out) : "l"(a), "l"(b))
#define UNPACK_F32X2(lo, hi, in) \
    asm("mov.b64 {%0, %1}, %2;" : "=f"(lo), "=f"(hi) : "l"(in))

__global__ __launch_bounds__(NTHREADS, 4)
void tropical_kernel(const float* __restrict__ x,     // [N, IN]
                     const float* __restrict__ w,     // [OUT, IN]
                     const float* __restrict__ bias,  // [OUT]
                     float* __restrict__ out)         // [N, OUT]
{
    __shared__ float xs[2][BN][ROWF];   // 9.2 KB
    __shared__ float ws[2][BO][ROWF];   // 18.4 KB
    __shared__ int   s_last;

    const int t = threadIdx.x;
    const int o_base = blockIdx.x * BO;
    const int n_base = blockIdx.y * BN;
    const int kc0    = blockIdx.z * (NCH * CHUNK);

    const int tx = t & 15;              // o rows: tx + j*16
    const int ty = t >> 4;              // n rows: ty + i*8

    float acc[4][4];
    #pragma unroll
    for (int i = 0; i < 4; i++)
        #pragma unroll
        for (int j = 0; j < 4; j++)
            acc[i][j] = -CUDART_INF_F;

    // ---- async fill of one chunk into buffer b (6 cp.async / thread) ----
    #define FILL(b, kc) do {                                                       \
        _Pragma("unroll")                                                          \
        for (int i = 0; i < 2; i++) {      /* xs: 32 rows x 8 f4 */                \
            int idx = t + i * NTHREADS; int row = idx >> 3; int c4 = idx & 7;      \
            cp_async16(smem_u32(&xs[b][row][c4 * 4]),                              \
                       &x[(n_base + row) * IN_TOT + (kc) + c4 * 4]);               \
        }                                                                          \
        _Pragma("unroll")                                                          \
        for (int i = 0; i < 4; i++) {      /* ws: 64 rows x 8 f4 */                \
            int idx = t + i * NTHREADS; int row = idx >> 3; int c4 = idx & 7;      \
            cp_async16(smem_u32(&ws[b][row][c4 * 4]),                              \
                       &w[(o_base + row) * IN_TOT + (kc) + c4 * 4]);               \
        }                                                                          \
        asm volatile("cp.async.commit_group;" ::: "memory");                       \
    } while (0)

    // ---- compute one chunk: per k4, per (i,j): 2 FADD2 + 4 FMNMX ----
    #define COMPUTE(b) do {                                                        \
        _Pragma("unroll")                                                          \
        for (int k4 = 0; k4 < CHUNK / 4; k4++) {                                   \
            ulonglong2 xv[4];                                                      \
            _Pragma("unroll")                                                      \
            for (int i = 0; i < 4; i++)                                            \
                xv[i] = *reinterpret_cast<const ulonglong2*>(                      \
                    &xs[b][ty + i * 8][k4 * 4]);                                   \
            _Pragma("unroll")                                                      \
            for (int j = 0; j < 4; j++) {                                          \
                ulonglong2 wv = *reinterpret_cast<const ulonglong2*>(              \
                    &ws[b][tx + j * 16][k4 * 4]);                                  \
                _Pragma("unroll")                                                  \
                for (int i = 0; i < 4; i++) {                                      \
                    unsigned long long s0, s1;                                     \
                    ADD_F32X2(s0, xv[i].x, wv.x);                                  \
                    ADD_F32X2(s1, xv[i].y, wv.y);                                  \
                    float a0, a1, b0, b1;                                          \
                    UNPACK_F32X2(a0, a1, s0);                                      \
                    UNPACK_F32X2(b0, b1, s1);                                      \
                    float m = fmaxf(fmaxf(a0, a1), fmaxf(b0, b1));                 \
                    acc[i][j] = fmaxf(acc[i][j], m);                               \
                }                                                                  \
            }                                                                      \
        }                                                                          \
    } while (0)

    // ---- 2-stage pipeline over 4 chunks ----
    FILL(0, kc0);
    FILL(1, kc0 + CHUNK);

    asm volatile("cp.async.wait_group 1;" ::: "memory");   // chunk0 resident
    __syncthreads();
    COMPUTE(0);

    __syncthreads();                                       // all done reading buf0
    FILL(0, kc0 + 2 * CHUNK);
    asm volatile("cp.async.wait_group 1;" ::: "memory");   // chunk1 resident
    __syncthreads();
    COMPUTE(1);

    __syncthreads();                                       // all done reading buf1
    FILL(1, kc0 + 3 * CHUNK);
    asm volatile("cp.async.wait_group 1;" ::: "memory");   // chunk2 resident
    __syncthreads();
    COMPUTE(0);

    asm volatile("cp.async.wait_group 0;" ::: "memory");   // chunk3 resident
    __syncthreads();
    COMPUTE(1);

    // ---- write split-K partial ----
    float* p = g_partial + blockIdx.z * (N_TOT * OUT_TOT);
    #pragma unroll
    for (int i = 0; i < 4; i++) {
        #pragma unroll
        for (int j = 0; j < 4; j++) {
            p[(n_base + ty + i * 8) * OUT_TOT + o_base + tx + j * 16] = acc[i][j];
        }
    }

    // ---- last CTA per (n,o)-tile reduces across kz ----
    __threadfence();
    __syncthreads();
    const int tile = blockIdx.y * TILES_O + blockIdx.x;
    if (t == 0) {
        int old = atomicAdd(&g_ticket[tile], 1);
        s_last = (old == KSPLIT - 1);
        if (s_last) g_ticket[tile] = 0;   // reset for next graph replay
    }
    __syncthreads();

    if (s_last) {
        __threadfence();   // acquire: all partials visible
        #pragma unroll
        for (int j = 0; j < 4; j++) {
            int f    = j * NTHREADS + t;         // 512 float4 per tile
            int ln   = f >> 4;                   // 16 float4 per 64-o row
            int lo4  = f & 15;
            int base = (n_base + ln) * OUT_TOT + o_base + lo4 * 4;

            float4 m = *reinterpret_cast<const float4*>(&g_partial[base]);
            #pragma unroll
            for (int z = 1; z < KSPLIT; z++) {
                float4 v = *reinterpret_cast<const float4*>(
                    &g_partial[z * (N_TOT * OUT_TOT) + base]);
                m.x = fmaxf(m.x, v.x);
                m.y = fmaxf(m.y, v.y);
                m.z = fmaxf(m.z, v.z);
                m.w = fmaxf(m.w, v.w);
            }
            float4 b = *reinterpret_cast<const float4*>(&bias[o_base + lo4 * 4]);
            m.x += b.x; m.y += b.y; m.z += b.z; m.w += b.w;
            *reinterpret_cast<float4*>(&out[base]) = m;
        }
    }
}

extern "C" void kernel_launch(void* const* d_in, const int* in_sizes, int n_in,
                              void* d_out, int out_size) {
    const float* x    = (const float*)d_in[0];   // [128, 1024]
    const float* w    = (const float*)d_in[1];   // [1024, 1024]
    const float* bias = (const float*)d_in[2];   // [1024]
    float* out        = (float*)d_out;           // [128, 1024]

    dim3 grid(TILES_O, TILES_N, KSPLIT);         // 16 x 4 x 8 = 512 CTAs
    tropical_kernel<<<grid, NTHREADS>>>(x, w, bias, out);
}